// round 1
// baseline (speedup 1.0000x reference)
#include <cuda_runtime.h>
#include <math.h>

#define NB 2
#define NT 2048
#define ND 1024
#define NH 16
#define NHD 64
#define NM (NB*NT)   // 4096 rows

// Scratch (allocation-free rule: __device__ globals)
__device__ float g_q[NB*NT*ND];
__device__ float g_k[NB*NT*ND];
__device__ float g_v[NB*NT*ND];
__device__ float g_attn[NB*NT*ND];

// ---------------------------------------------------------------------------
// Generic GEMM: C = A @ W^T + bias,  A[M,1024], W[1024,1024] (row-major)
// mode 0: C[row*ND + col] plain
// mode 1: RoPE then write to [B,H,T,HD]
// mode 2: write to [B,H,T,HD] (no RoPE)
// Block tile 128x128, BK=16, 256 threads, 8x8 per thread.
// Column mapping pair-interleaved: col = 2*cm + (j&1) + 32*(j>>1), so RoPE
// pairs live in one thread and smem B-reads are conflict-free.
// ---------------------------------------------------------------------------
__global__ __launch_bounds__(256) void gemm_bias_kernel(
    const float* __restrict__ A, const float* __restrict__ W,
    const float* __restrict__ bias, float* __restrict__ C,
    int mode, const float* __restrict__ cosp, const float* __restrict__ sinp)
{
    __shared__ float As[16][128];   // [k][m]
    __shared__ float Bs[16][128];   // [k][n]
    const int tid = threadIdx.x;
    const int bm = blockIdx.y * 128;
    const int bn = blockIdx.x * 128;
    const int rm = tid >> 4;        // 0..15
    const int cm = tid & 15;        // 0..15

    float acc[8][8];
#pragma unroll
    for (int i = 0; i < 8; i++)
#pragma unroll
        for (int j = 0; j < 8; j++) acc[i][j] = 0.f;

    int ro[8], co[8];
#pragma unroll
    for (int i = 0; i < 8; i++) {
        ro[i] = 2*rm + (i & 1) + 32*(i >> 1);
        co[i] = 2*cm + (i & 1) + 32*(i >> 1);
    }

    for (int k0 = 0; k0 < ND; k0 += 16) {
#pragma unroll
        for (int qq = 0; qq < 2; qq++) {
            int s   = tid*2 + qq;          // 0..511
            int row = s >> 2;              // 0..127
            int kc  = (s & 3) * 4;         // 0,4,8,12
            const float4 a4 = *(const float4*)(A + (size_t)(bm+row)*ND + k0 + kc);
            As[kc+0][row] = a4.x; As[kc+1][row] = a4.y;
            As[kc+2][row] = a4.z; As[kc+3][row] = a4.w;
            const float4 w4 = *(const float4*)(W + (size_t)(bn+row)*ND + k0 + kc);
            Bs[kc+0][row] = w4.x; Bs[kc+1][row] = w4.y;
            Bs[kc+2][row] = w4.z; Bs[kc+3][row] = w4.w;
        }
        __syncthreads();
#pragma unroll
        for (int kk = 0; kk < 16; kk++) {
            float a[8], b[8];
#pragma unroll
            for (int i = 0; i < 8; i++) a[i] = As[kk][ro[i]];
#pragma unroll
            for (int j = 0; j < 8; j++) b[j] = Bs[kk][co[j]];
#pragma unroll
            for (int i = 0; i < 8; i++)
#pragma unroll
                for (int j = 0; j < 8; j++)
                    acc[i][j] = fmaf(a[i], b[j], acc[i][j]);
        }
        __syncthreads();
    }

    // Epilogue
#pragma unroll
    for (int i = 0; i < 8; i++) {
        const int grow = bm + ro[i];            // global token row 0..4095
        const int bb   = grow >> 11;            // batch (T = 2048)
        const int t    = grow & (NT - 1);
#pragma unroll
        for (int jp = 0; jp < 4; jp++) {
            const int gcol = bn + 2*cm + 32*jp; // even column
            float ve = acc[i][2*jp]   + bias[gcol];
            float vo = acc[i][2*jp+1] + bias[gcol+1];
            if (mode == 0) {
                *(float2*)(C + (size_t)grow*ND + gcol) = make_float2(ve, vo);
            } else {
                const int h  = gcol >> 6;
                const int dd = gcol & 63;       // even
                float* outp = C + ((((size_t)bb*NH + h)*NT + t)*NHD) + dd;
                if (mode == 1) {
                    const int pp = dd >> 1;
                    float cv = cosp[t*32 + pp];
                    float sv = sinp[t*32 + pp];
                    *(float2*)outp = make_float2(ve*cv - vo*sv, ve*sv + vo*cv);
                } else {
                    *(float2*)outp = make_float2(ve, vo);
                }
            }
        }
    }
}

// ---------------------------------------------------------------------------
// Flash attention, fp32, causal. One block per (q-tile of 64, head, batch).
// 256 threads; per-thread 4x4 S-tile interleaved (rows rm+16i, cols cm+16j).
// Smem: Qs[d][row], KPs (K as [d][col], reused as P[row][kcol]), Vs[k][d].
// Exactly 48KB static shared.
// ---------------------------------------------------------------------------
__global__ __launch_bounds__(256) void attn_kernel(
    const float* __restrict__ q, const float* __restrict__ k,
    const float* __restrict__ v, float* __restrict__ o)
{
    __shared__ float Qs[64*64];   // [d*64 + row]
    __shared__ float KPs[64*64];  // K: [d*64 + col]; later P: [row*64 + kcol]
    __shared__ float Vs[64*64];   // [kk*64 + d]

    const int tid = threadIdx.x;
    const int qt = blockIdx.x, h = blockIdx.y, b = blockIdx.z;
    const float* qb = q + (((size_t)b*NH + h)*NT + (size_t)qt*64)*NHD;
    const float* kb = k + (((size_t)b*NH + h)*NT)*NHD;
    const float* vb = v + (((size_t)b*NH + h)*NT)*NHD;
    const int rm = tid >> 4, cm = tid & 15;

    int rows[4], cols[4];
#pragma unroll
    for (int i = 0; i < 4; i++) { rows[i] = rm + 16*i; cols[i] = cm + 16*i; }

    // Load Q tile transposed into Qs[d][row]
#pragma unroll
    for (int ql = 0; ql < 4; ql++) {
        int s = tid + 256*ql;        // 0..1023 float4 slots
        int row = s >> 4;
        int c4 = (s & 15) * 4;
        float4 v4 = *(const float4*)(qb + row*NHD + c4);
        Qs[(c4+0)*64+row] = v4.x; Qs[(c4+1)*64+row] = v4.y;
        Qs[(c4+2)*64+row] = v4.z; Qs[(c4+3)*64+row] = v4.w;
    }

    float m_i[4], l_i[4], acc[4][4];
#pragma unroll
    for (int i = 0; i < 4; i++) {
        m_i[i] = -1e30f; l_i[i] = 0.f;
#pragma unroll
        for (int j = 0; j < 4; j++) acc[i][j] = 0.f;
    }

    for (int kt = 0; kt <= qt; kt++) {
        __syncthreads();   // Q loaded (first iter); prev PV done (later iters)
        // Load K (transposed) and V tiles
#pragma unroll
        for (int ql = 0; ql < 4; ql++) {
            int s = tid + 256*ql;
            int row = s >> 4;
            int c4 = (s & 15) * 4;
            float4 kv = *(const float4*)(kb + (size_t)(kt*64+row)*NHD + c4);
            KPs[(c4+0)*64+row] = kv.x; KPs[(c4+1)*64+row] = kv.y;
            KPs[(c4+2)*64+row] = kv.z; KPs[(c4+3)*64+row] = kv.w;
            float4 vv = *(const float4*)(vb + (size_t)(kt*64+row)*NHD + c4);
            *(float4*)(Vs + row*64 + c4) = vv;
        }
        __syncthreads();

        // S = Q K^T
        float sc[4][4];
#pragma unroll
        for (int i = 0; i < 4; i++)
#pragma unroll
            for (int j = 0; j < 4; j++) sc[i][j] = 0.f;
#pragma unroll 4
        for (int d = 0; d < 64; d++) {
            float qv[4], kv[4];
#pragma unroll
            for (int i = 0; i < 4; i++) qv[i] = Qs[d*64 + rows[i]];
#pragma unroll
            for (int j = 0; j < 4; j++) kv[j] = KPs[d*64 + cols[j]];
#pragma unroll
            for (int i = 0; i < 4; i++)
#pragma unroll
                for (int j = 0; j < 4; j++)
                    sc[i][j] = fmaf(qv[i], kv[j], sc[i][j]);
        }

        // Scale, causal mask, online softmax update
#pragma unroll
        for (int i = 0; i < 4; i++) {
            const int qi = qt*64 + rows[i];
            float mloc = -1e30f;
#pragma unroll
            for (int j = 0; j < 4; j++) {
                const int kj = kt*64 + cols[j];
                float val = sc[i][j] * 0.125f;
                if (kj > qi) val = -1e30f;
                sc[i][j] = val;
                mloc = fmaxf(mloc, val);
            }
#pragma unroll
            for (int off = 8; off >= 1; off >>= 1)
                mloc = fmaxf(mloc, __shfl_xor_sync(0xffffffffu, mloc, off));
            const float m_new = fmaxf(m_i[i], mloc);
            const float alpha = __expf(m_i[i] - m_new);
            float psum = 0.f;
#pragma unroll
            for (int j = 0; j < 4; j++) {
                float p = __expf(sc[i][j] - m_new);
                sc[i][j] = p;
                psum += p;
            }
#pragma unroll
            for (int off = 8; off >= 1; off >>= 1)
                psum += __shfl_xor_sync(0xffffffffu, psum, off);
            l_i[i] = l_i[i]*alpha + psum;
            m_i[i] = m_new;
#pragma unroll
            for (int j = 0; j < 4; j++) acc[i][j] *= alpha;
        }

        __syncthreads();   // everyone done reading K before P overwrites
#pragma unroll
        for (int i = 0; i < 4; i++)
#pragma unroll
            for (int j = 0; j < 4; j++)
                KPs[rows[i]*64 + cols[j]] = sc[i][j];
        __syncthreads();

        // O += P V
#pragma unroll 4
        for (int kk = 0; kk < 64; kk++) {
            float pv[4], vv[4];
#pragma unroll
            for (int i = 0; i < 4; i++) pv[i] = KPs[rows[i]*64 + kk];
#pragma unroll
            for (int j = 0; j < 4; j++) vv[j] = Vs[kk*64 + cols[j]];
#pragma unroll
            for (int i = 0; i < 4; i++)
#pragma unroll
                for (int j = 0; j < 4; j++)
                    acc[i][j] = fmaf(pv[i], vv[j], acc[i][j]);
        }
    }

    // Write output into [B,T,D]
#pragma unroll
    for (int i = 0; i < 4; i++) {
        const float inv = 1.f / l_i[i];
        const int qi = qt*64 + rows[i];
        float* op = o + ((size_t)b*NT + qi)*ND + h*NHD;
#pragma unroll
        for (int j = 0; j < 4; j++)
            op[cols[j]] = acc[i][j] * inv;
    }
}

// ---------------------------------------------------------------------------
extern "C" void kernel_launch(void* const* d_in, const int* in_sizes, int n_in,
                              void* d_out, int out_size)
{
    (void)in_sizes; (void)n_in; (void)out_size;
    const float* x    = (const float*)d_in[0];
    const float* cosp = (const float*)d_in[1];
    const float* sinp = (const float*)d_in[2];
    const float* Wq   = (const float*)d_in[3];
    const float* bq   = (const float*)d_in[4];
    const float* Wk   = (const float*)d_in[5];
    const float* bk   = (const float*)d_in[6];
    const float* Wv   = (const float*)d_in[7];
    const float* bv   = (const float*)d_in[8];
    const float* Wo   = (const float*)d_in[9];
    const float* bo   = (const float*)d_in[10];
    float* out = (float*)d_out;

    float *qp, *kp, *vp, *ap;
    cudaGetSymbolAddress((void**)&qp, g_q);
    cudaGetSymbolAddress((void**)&kp, g_k);
    cudaGetSymbolAddress((void**)&vp, g_v);
    cudaGetSymbolAddress((void**)&ap, g_attn);

    dim3 gg(ND/128, NM/128);   // (8, 32)
    gemm_bias_kernel<<<gg, 256>>>(x, Wq, bq, qp, 1, cosp, sinp);
    gemm_bias_kernel<<<gg, 256>>>(x, Wk, bk, kp, 1, cosp, sinp);
    gemm_bias_kernel<<<gg, 256>>>(x, Wv, bv, vp, 2, nullptr, nullptr);

    dim3 ga(NT/64, NH, NB);    // (32, 16, 2)
    attn_kernel<<<ga, 256>>>(qp, kp, vp, ap);

    gemm_bias_kernel<<<gg, 256>>>(ap, Wo, bo, out, 0, nullptr, nullptr);
}

// round 2
// speedup vs baseline: 1.0377x; 1.0377x over previous
#include <cuda_runtime.h>
#include <math.h>

#define NB 2
#define NT 2048
#define ND 1024
#define NH 16
#define NHD 64
#define NM (NB*NT)   // 4096 rows

// Scratch (allocation-free rule: __device__ globals)
__device__ float g_q[NB*NT*ND];
__device__ float g_k[NB*NT*ND];
__device__ float g_v[NB*NT*ND];
__device__ float g_attn[NB*NT*ND];

// ---------------------------------------------------------------------------
// Generic GEMM: C = A @ W^T + bias,  A[M,1024], W[1024,1024] (row-major)
// mode 0: C[row*ND + col] plain
// mode 1: RoPE then write to [B,H,T,HD]
// mode 2: write to [B,H,T,HD] (no RoPE)
// Block tile 128x128, BK=16, 256 threads, 8x8 per thread.
// Smem swizzle on the m/n index: m ^ (((k>>3)&1)<<4) -> conflict-free
// transposed stores AND conflict-free compute reads.
// Register double-buffering of global tile loads.
// ---------------------------------------------------------------------------
__global__ __launch_bounds__(256) void gemm_bias_kernel(
    const float* __restrict__ A, const float* __restrict__ W,
    const float* __restrict__ bias, float* __restrict__ C,
    int mode, const float* __restrict__ cosp, const float* __restrict__ sinp)
{
    __shared__ float As[16*128];   // element (k,m) at k*128 + (m ^ xb(k))
    __shared__ float Bs[16*128];
    const int tid = threadIdx.x;
    const int bm = blockIdx.y * 128;
    const int bn = blockIdx.x * 128;
    const int rm = tid >> 4;        // 0..15
    const int cm = tid & 15;        // 0..15

    float acc[8][8];
#pragma unroll
    for (int i = 0; i < 8; i++)
#pragma unroll
        for (int j = 0; j < 8; j++) acc[i][j] = 0.f;

    int ro[8], co[8];
#pragma unroll
    for (int i = 0; i < 8; i++) {
        ro[i] = 2*rm + (i & 1) + 32*(i >> 1);
        co[i] = 2*cm + (i & 1) + 32*(i >> 1);
    }

    // per-thread load coords
    int lrow[2], lkc[2];
#pragma unroll
    for (int qq = 0; qq < 2; qq++) {
        int s   = tid*2 + qq;          // 0..511
        lrow[qq] = s >> 2;             // 0..127
        lkc[qq]  = (s & 3) * 4;        // 0,4,8,12
    }

    float4 pa[2], pw[2];
#pragma unroll
    for (int qq = 0; qq < 2; qq++) {
        pa[qq] = *(const float4*)(A + (size_t)(bm+lrow[qq])*ND + lkc[qq]);
        pw[qq] = *(const float4*)(W + (size_t)(bn+lrow[qq])*ND + lkc[qq]);
    }

    for (int k0 = 0; k0 < ND; k0 += 16) {
#pragma unroll
        for (int qq = 0; qq < 2; qq++) {
            const int row = lrow[qq], kc = lkc[qq];
            const int col = row ^ (((kc >> 3) & 1) << 4);  // same for kc..kc+3
            As[(kc+0)*128+col] = pa[qq].x; As[(kc+1)*128+col] = pa[qq].y;
            As[(kc+2)*128+col] = pa[qq].z; As[(kc+3)*128+col] = pa[qq].w;
            Bs[(kc+0)*128+col] = pw[qq].x; Bs[(kc+1)*128+col] = pw[qq].y;
            Bs[(kc+2)*128+col] = pw[qq].z; Bs[(kc+3)*128+col] = pw[qq].w;
        }
        __syncthreads();
        if (k0 + 16 < ND) {
#pragma unroll
            for (int qq = 0; qq < 2; qq++) {
                pa[qq] = *(const float4*)(A + (size_t)(bm+lrow[qq])*ND + k0+16 + lkc[qq]);
                pw[qq] = *(const float4*)(W + (size_t)(bn+lrow[qq])*ND + k0+16 + lkc[qq]);
            }
        }
#pragma unroll
        for (int kk = 0; kk < 16; kk++) {
            const int xr = ((kk >> 3) & 1) << 4;
            float a[8], b[8];
#pragma unroll
            for (int i = 0; i < 8; i++) a[i] = As[kk*128 + (ro[i]^xr)];
#pragma unroll
            for (int j = 0; j < 8; j++) b[j] = Bs[kk*128 + (co[j]^xr)];
#pragma unroll
            for (int i = 0; i < 8; i++)
#pragma unroll
                for (int j = 0; j < 8; j++)
                    acc[i][j] = fmaf(a[i], b[j], acc[i][j]);
        }
        __syncthreads();
    }

    // Epilogue
#pragma unroll
    for (int i = 0; i < 8; i++) {
        const int grow = bm + ro[i];            // global token row 0..4095
        const int bb   = grow >> 11;            // batch (T = 2048)
        const int t    = grow & (NT - 1);
#pragma unroll
        for (int jp = 0; jp < 4; jp++) {
            const int gcol = bn + 2*cm + 32*jp; // even column
            float ve = acc[i][2*jp]   + bias[gcol];
            float vo = acc[i][2*jp+1] + bias[gcol+1];
            if (mode == 0) {
                *(float2*)(C + (size_t)grow*ND + gcol) = make_float2(ve, vo);
            } else {
                const int h  = gcol >> 6;
                const int dd = gcol & 63;       // even
                float* outp = C + ((((size_t)bb*NH + h)*NT + t)*NHD) + dd;
                if (mode == 1) {
                    const int pp = dd >> 1;
                    float cv = cosp[t*32 + pp];
                    float sv = sinp[t*32 + pp];
                    *(float2*)outp = make_float2(ve*cv - vo*sv, ve*sv + vo*cv);
                } else {
                    *(float2*)outp = make_float2(ve, vo);
                }
            }
        }
    }
}

// ---------------------------------------------------------------------------
// Flash attention, fp32, causal. One block per (q-tile of 64, head, batch).
// 256 threads; per-thread 4x4 S-tile interleaved (rows rm+16i, cols cm+16j).
// Smem (48KB static):
//   Qs/Ks transposed with swizzle: (d, r) at d*64 + ((r + 2*(d>>2)) & 63)
//     -> conflict-free transpose stores AND conflict-free compute reads.
//   P overlaid on K buffer: (r, kk) at r*64 + (kk ^ ((r&1)<<4))
//     -> odd/even row-groups hit disjoint bank halves; conflict-free.
//   Vs natural [kk][d].
// ---------------------------------------------------------------------------
__global__ __launch_bounds__(256) void attn_kernel(
    const float* __restrict__ q, const float* __restrict__ k,
    const float* __restrict__ v, float* __restrict__ o)
{
    __shared__ float Qs[64*64];   // swizzled transposed
    __shared__ float KPs[64*64];  // K swizzled transposed; later P
    __shared__ float Vs[64*64];   // [kk][d]

    const int tid = threadIdx.x;
    const int qt = blockIdx.x, h = blockIdx.y, b = blockIdx.z;
    const float* qb = q + (((size_t)b*NH + h)*NT + (size_t)qt*64)*NHD;
    const float* kb = k + (((size_t)b*NH + h)*NT)*NHD;
    const float* vb = v + (((size_t)b*NH + h)*NT)*NHD;
    const int rm = tid >> 4, cm = tid & 15;
    const int pxor = (rm & 1) << 4;   // P-phase swizzle (rows share rm parity)

    int rows[4], cols[4];
#pragma unroll
    for (int i = 0; i < 4; i++) { rows[i] = rm + 16*i; cols[i] = cm + 16*i; }

    // Load Q tile transposed+swizzled
#pragma unroll
    for (int ql = 0; ql < 4; ql++) {
        int s = tid + 256*ql;        // 0..1023 float4 slots
        int row = s >> 4;
        int c4 = (s & 15) * 4;
        float4 v4 = *(const float4*)(qb + row*NHD + c4);
        int col = (row + ((c4 >> 2) << 1)) & 63;
        Qs[(c4+0)*64+col] = v4.x; Qs[(c4+1)*64+col] = v4.y;
        Qs[(c4+2)*64+col] = v4.z; Qs[(c4+3)*64+col] = v4.w;
    }

    float m_i[4], l_i[4], acc[4][4];
#pragma unroll
    for (int i = 0; i < 4; i++) {
        m_i[i] = -1e30f; l_i[i] = 0.f;
#pragma unroll
        for (int j = 0; j < 4; j++) acc[i][j] = 0.f;
    }

    for (int kt = 0; kt <= qt; kt++) {
        __syncthreads();   // Q loaded (first iter); prev PV done (later iters)
        // Load K (transposed+swizzled) and V tiles
#pragma unroll
        for (int ql = 0; ql < 4; ql++) {
            int s = tid + 256*ql;
            int row = s >> 4;
            int c4 = (s & 15) * 4;
            float4 kv = *(const float4*)(kb + (size_t)(kt*64+row)*NHD + c4);
            int col = (row + ((c4 >> 2) << 1)) & 63;
            KPs[(c4+0)*64+col] = kv.x; KPs[(c4+1)*64+col] = kv.y;
            KPs[(c4+2)*64+col] = kv.z; KPs[(c4+3)*64+col] = kv.w;
            float4 vv = *(const float4*)(vb + (size_t)(kt*64+row)*NHD + c4);
            *(float4*)(Vs + row*64 + c4) = vv;
        }
        __syncthreads();

        // S = Q K^T
        float sc[4][4];
#pragma unroll
        for (int i = 0; i < 4; i++)
#pragma unroll
            for (int j = 0; j < 4; j++) sc[i][j] = 0.f;
#pragma unroll 4
        for (int d = 0; d < 64; d++) {
            const int sw = (d >> 2) << 1;
            float qv[4], kv[4];
#pragma unroll
            for (int i = 0; i < 4; i++) qv[i] = Qs[d*64 + ((rows[i] + sw) & 63)];
#pragma unroll
            for (int j = 0; j < 4; j++) kv[j] = KPs[d*64 + ((cols[j] + sw) & 63)];
#pragma unroll
            for (int i = 0; i < 4; i++)
#pragma unroll
                for (int j = 0; j < 4; j++)
                    sc[i][j] = fmaf(qv[i], kv[j], sc[i][j]);
        }

        // Scale, causal mask, online softmax update
#pragma unroll
        for (int i = 0; i < 4; i++) {
            const int qi = qt*64 + rows[i];
            float mloc = -1e30f;
#pragma unroll
            for (int j = 0; j < 4; j++) {
                const int kj = kt*64 + cols[j];
                float val = sc[i][j] * 0.125f;
                if (kj > qi) val = -1e30f;
                sc[i][j] = val;
                mloc = fmaxf(mloc, val);
            }
#pragma unroll
            for (int off = 8; off >= 1; off >>= 1)
                mloc = fmaxf(mloc, __shfl_xor_sync(0xffffffffu, mloc, off));
            const float m_new = fmaxf(m_i[i], mloc);
            const float alpha = __expf(m_i[i] - m_new);
            float psum = 0.f;
#pragma unroll
            for (int j = 0; j < 4; j++) {
                float p = __expf(sc[i][j] - m_new);
                sc[i][j] = p;
                psum += p;
            }
#pragma unroll
            for (int off = 8; off >= 1; off >>= 1)
                psum += __shfl_xor_sync(0xffffffffu, psum, off);
            l_i[i] = l_i[i]*alpha + psum;
            m_i[i] = m_new;
#pragma unroll
            for (int j = 0; j < 4; j++) acc[i][j] *= alpha;
        }

        __syncthreads();   // everyone done reading K before P overwrites
#pragma unroll
        for (int i = 0; i < 4; i++)
#pragma unroll
            for (int j = 0; j < 4; j++)
                KPs[rows[i]*64 + (cols[j] ^ pxor)] = sc[i][j];
        __syncthreads();

        // O += P V
#pragma unroll 4
        for (int kk = 0; kk < 64; kk++) {
            float pv[4], vv[4];
#pragma unroll
            for (int i = 0; i < 4; i++) pv[i] = KPs[rows[i]*64 + (kk ^ pxor)];
#pragma unroll
            for (int j = 0; j < 4; j++) vv[j] = Vs[kk*64 + cols[j]];
#pragma unroll
            for (int i = 0; i < 4; i++)
#pragma unroll
                for (int j = 0; j < 4; j++)
                    acc[i][j] = fmaf(pv[i], vv[j], acc[i][j]);
        }
    }

    // Write output into [B,T,D]
#pragma unroll
    for (int i = 0; i < 4; i++) {
        const float inv = 1.f / l_i[i];
        const int qi = qt*64 + rows[i];
        float* op = o + ((size_t)b*NT + qi)*ND + h*NHD;
#pragma unroll
        for (int j = 0; j < 4; j++)
            op[cols[j]] = acc[i][j] * inv;
    }
}

// ---------------------------------------------------------------------------
extern "C" void kernel_launch(void* const* d_in, const int* in_sizes, int n_in,
                              void* d_out, int out_size)
{
    (void)in_sizes; (void)n_in; (void)out_size;
    const float* x    = (const float*)d_in[0];
    const float* cosp = (const float*)d_in[1];
    const float* sinp = (const float*)d_in[2];
    const float* Wq   = (const float*)d_in[3];
    const float* bq   = (const float*)d_in[4];
    const float* Wk   = (const float*)d_in[5];
    const float* bk   = (const float*)d_in[6];
    const float* Wv   = (const float*)d_in[7];
    const float* bv   = (const float*)d_in[8];
    const float* Wo   = (const float*)d_in[9];
    const float* bo   = (const float*)d_in[10];
    float* out = (float*)d_out;

    float *qp, *kp, *vp, *ap;
    cudaGetSymbolAddress((void**)&qp, g_q);
    cudaGetSymbolAddress((void**)&kp, g_k);
    cudaGetSymbolAddress((void**)&vp, g_v);
    cudaGetSymbolAddress((void**)&ap, g_attn);

    dim3 gg(ND/128, NM/128);   // (8, 32)
    gemm_bias_kernel<<<gg, 256>>>(x, Wq, bq, qp, 1, cosp, sinp);
    gemm_bias_kernel<<<gg, 256>>>(x, Wk, bk, kp, 1, cosp, sinp);
    gemm_bias_kernel<<<gg, 256>>>(x, Wv, bv, vp, 2, nullptr, nullptr);

    dim3 ga(NT/64, NH, NB);    // (32, 16, 2)
    attn_kernel<<<ga, 256>>>(qp, kp, vp, ap);

    gemm_bias_kernel<<<gg, 256>>>(ap, Wo, bo, out, 0, nullptr, nullptr);
}

// round 4
// speedup vs baseline: 1.5190x; 1.4639x over previous
#include <cuda_runtime.h>
#include <cuda_bf16.h>
#include <math.h>
#include <stdint.h>

#define NB 2
#define NT 2048
#define ND 1024
#define NH 16
#define NHD 64
#define NM (NB*NT)   // 4096 rows

// ------------------------- scratch (__device__ globals) ---------------------
__device__ float g_q[NB*NT*ND];
__device__ float g_k[NB*NT*ND];
__device__ float g_v[NB*NT*ND];
__device__ float g_attn[NB*NT*ND];
__device__ __nv_bfloat16 g_xh[NM*ND];
__device__ __nv_bfloat16 g_xl[NM*ND];
__device__ __nv_bfloat16 g_wh[4*ND*ND];
__device__ __nv_bfloat16 g_wl[4*ND*ND];

// ------------------------- helpers ------------------------------------------
__device__ __forceinline__ uint32_t smem_u32(const void* p) {
    uint32_t a;
    asm("{ .reg .u64 t; cvta.to.shared.u64 t, %1; cvt.u32.u64 %0, t; }"
        : "=r"(a) : "l"(p));
    return a;
}
__device__ __forceinline__ void cpasync16(uint32_t dst, const void* src) {
    asm volatile("cp.async.ca.shared.global [%0], [%1], 16;" :: "r"(dst), "l"(src));
}
#define CP_COMMIT() asm volatile("cp.async.commit_group;" ::: "memory")
#define CP_WAIT1()  asm volatile("cp.async.wait_group 1;" ::: "memory")

__device__ __forceinline__ void mma16816(float* d, const uint32_t* a, const uint32_t* b) {
    asm volatile("mma.sync.aligned.m16n8k16.row.col.f32.bf16.bf16.f32 "
        "{%0,%1,%2,%3}, {%4,%5,%6,%7}, {%8,%9}, {%0,%1,%2,%3};"
        : "+f"(d[0]), "+f"(d[1]), "+f"(d[2]), "+f"(d[3])
        : "r"(a[0]), "r"(a[1]), "r"(a[2]), "r"(a[3]), "r"(b[0]), "r"(b[1]));
}

// ------------------------- fp32 -> bf16 hi/lo split --------------------------
__global__ __launch_bounds__(256) void split_kernel(
    const float* __restrict__ s, __nv_bfloat16* __restrict__ h,
    __nv_bfloat16* __restrict__ l, int n4)
{
    int i = blockIdx.x * blockDim.x + threadIdx.x;
    if (i >= n4) return;
    float4 v = ((const float4*)s)[i];
    __nv_bfloat16 h0 = __float2bfloat16(v.x), h1 = __float2bfloat16(v.y);
    __nv_bfloat16 h2 = __float2bfloat16(v.z), h3 = __float2bfloat16(v.w);
    __nv_bfloat162* hp = (__nv_bfloat162*)h;
    hp[2*i]   = __nv_bfloat162(h0, h1);
    hp[2*i+1] = __nv_bfloat162(h2, h3);
    __nv_bfloat162* lp = (__nv_bfloat162*)l;
    lp[2*i]   = __nv_bfloat162(__float2bfloat16(v.x - __bfloat162float(h0)),
                               __float2bfloat16(v.y - __bfloat162float(h1)));
    lp[2*i+1] = __nv_bfloat162(__float2bfloat16(v.z - __bfloat162float(h2)),
                               __float2bfloat16(v.w - __bfloat162float(h3)));
}

__global__ __launch_bounds__(256) void split_w_kernel(
    const float* __restrict__ w0, const float* __restrict__ w1,
    const float* __restrict__ w2, const float* __restrict__ w3,
    __nv_bfloat16* __restrict__ h, __nv_bfloat16* __restrict__ l)
{
    int z = blockIdx.z;
    const float* src = (z == 0) ? w0 : (z == 1) ? w1 : (z == 2) ? w2 : w3;
    int i = blockIdx.x * blockDim.x + threadIdx.x;
    size_t base2 = (size_t)z * (ND*ND/2);
    float4 v = ((const float4*)src)[i];
    __nv_bfloat16 h0 = __float2bfloat16(v.x), h1 = __float2bfloat16(v.y);
    __nv_bfloat16 h2 = __float2bfloat16(v.z), h3 = __float2bfloat16(v.w);
    __nv_bfloat162* hp = (__nv_bfloat162*)h + base2;
    hp[2*i]   = __nv_bfloat162(h0, h1);
    hp[2*i+1] = __nv_bfloat162(h2, h3);
    __nv_bfloat162* lp = (__nv_bfloat162*)l + base2;
    lp[2*i]   = __nv_bfloat162(__float2bfloat16(v.x - __bfloat162float(h0)),
                               __float2bfloat16(v.y - __bfloat162float(h1)));
    lp[2*i+1] = __nv_bfloat162(__float2bfloat16(v.z - __bfloat162float(h2)),
                               __float2bfloat16(v.w - __bfloat162float(h3)));
}

// ------------------------- mma.sync bf16x3 GEMM ------------------------------
// C = A @ W^T + bias.  Tile 128x128, BK=32, 8 warps (2x4), cp.async x2 buffer.
// Smem tile: 128 rows x 80B (32 bf16 payload + 16B pad) per plane.
#define BK 32
#define ROWB 80
#define TILE_BYTES (128*ROWB)          // 10240
#define STAGE_BYTES (4*TILE_BYTES)     // 40960
#define SMEM_TOTAL (2*STAGE_BYTES)     // 81920

__global__ __launch_bounds__(256, 1) void tgemm_kernel(
    const __nv_bfloat16* __restrict__ ah, const __nv_bfloat16* __restrict__ al,
    const __nv_bfloat16* __restrict__ whb, const __nv_bfloat16* __restrict__ wlb,
    const float* __restrict__ b0, const float* __restrict__ b1, const float* __restrict__ b2,
    float* __restrict__ c0, float* __restrict__ c1, float* __restrict__ c2,
    int modebase, const float* __restrict__ cosp, const float* __restrict__ sinp)
{
    extern __shared__ __align__(128) char smem[];
    const int tid = threadIdx.x;
    const int wid = tid >> 5, lane = tid & 31;
    const int z = blockIdx.z;
    const int bm = blockIdx.y * 128, bn = blockIdx.x * 128;
    const __nv_bfloat16* wh = whb + (size_t)z * ND * ND;
    const __nv_bfloat16* wl = wlb + (size_t)z * ND * ND;
    const float* bias = (z == 0) ? b0 : (z == 1) ? b1 : b2;
    float* C = (z == 0) ? c0 : (z == 1) ? c1 : c2;
    const int mode = modebase ? ((z == 2) ? 2 : 1) : 0;

    const int wr = wid >> 2;          // 0..1  : 64-row group
    const int wc = wid & 3;           // 0..3  : 32-col group
    const int fr = lane >> 2;         // 0..7
    const int fcb = (lane & 3) * 4;   // byte offset of 2-elem pair

    float acc[4][4][4];
#pragma unroll
    for (int mf = 0; mf < 4; mf++)
#pragma unroll
        for (int nf = 0; nf < 4; nf++)
#pragma unroll
            for (int r = 0; r < 4; r++) acc[mf][nf][r] = 0.f;

    const uint32_t sbase = smem_u32(smem);

    // stage loader: 2048 x 16B chunks / 256 threads = 8 cp.async each
    auto stage_load = [&](int buf, int k0) {
        const uint32_t sb = sbase + buf * STAGE_BYTES;
        const __nv_bfloat16* srcs[4] = { ah, al, wh, wl };
#pragma unroll
        for (int tI = 0; tI < 4; tI++) {
            const int rb = (tI < 2) ? bm : bn;
#pragma unroll
            for (int i = 0; i < 2; i++) {
                int q = tid + 256 * i;          // 0..511
                int row = q >> 2, c = q & 3;
                cpasync16(sb + tI * TILE_BYTES + row * ROWB + c * 16,
                          srcs[tI] + (size_t)(rb + row) * ND + k0 + c * 8);
            }
        }
    };

    stage_load(0, 0);
    CP_COMMIT();

    const int NS = ND / BK;   // 32
    for (int st = 0; st < NS; st++) {
        if (st + 1 < NS) stage_load((st + 1) & 1, (st + 1) * BK);
        CP_COMMIT();
        CP_WAIT1();
        __syncthreads();

        const char* sg = smem + (st & 1) * STAGE_BYTES;
        const char* sAh = sg;
        const char* sAl = sg + TILE_BYTES;
        const char* sBh = sg + 2 * TILE_BYTES;
        const char* sBl = sg + 3 * TILE_BYTES;

#pragma unroll
        for (int ks = 0; ks < 2; ks++) {
            const int kb = ks * 32;   // 16 elems = 32B per k-step
            uint32_t Ah[4][4], Al[4][4], Bh[4][2], Bl[4][2];
#pragma unroll
            for (int mf = 0; mf < 4; mf++) {
                const int r0 = (wr * 64 + mf * 16 + fr) * ROWB + kb + fcb;
#pragma unroll
                for (int h8 = 0; h8 < 2; h8++) {      // rows +0 / +8
#pragma unroll
                    for (int k8 = 0; k8 < 2; k8++) {  // k +0 / +8 (16B)
                        const int off = r0 + h8 * 8 * ROWB + k8 * 16;
                        Ah[mf][h8 + 2*k8] = *(const uint32_t*)(sAh + off);
                        Al[mf][h8 + 2*k8] = *(const uint32_t*)(sAl + off);
                    }
                }
            }
#pragma unroll
            for (int nf = 0; nf < 4; nf++) {
                const int r0 = (wc * 32 + nf * 8 + fr) * ROWB + kb + fcb;
                Bh[nf][0] = *(const uint32_t*)(sBh + r0);
                Bh[nf][1] = *(const uint32_t*)(sBh + r0 + 16);
                Bl[nf][0] = *(const uint32_t*)(sBl + r0);
                Bl[nf][1] = *(const uint32_t*)(sBl + r0 + 16);
            }
            // pass-major: same-acc mmas are 16 apart (no RAW stall)
#pragma unroll
            for (int mf = 0; mf < 4; mf++)
#pragma unroll
                for (int nf = 0; nf < 4; nf++)
                    mma16816(acc[mf][nf], Ah[mf], Bh[nf]);
#pragma unroll
            for (int mf = 0; mf < 4; mf++)
#pragma unroll
                for (int nf = 0; nf < 4; nf++)
                    mma16816(acc[mf][nf], Ah[mf], Bl[nf]);
#pragma unroll
            for (int mf = 0; mf < 4; mf++)
#pragma unroll
                for (int nf = 0; nf < 4; nf++)
                    mma16816(acc[mf][nf], Al[mf], Bh[nf]);
        }
        __syncthreads();
    }

    // ------------- epilogue -------------
#pragma unroll
    for (int mf = 0; mf < 4; mf++) {
#pragma unroll
        for (int h8 = 0; h8 < 2; h8++) {
            const int grow = bm + wr * 64 + mf * 16 + fr + h8 * 8;
            const int bb = grow >> 11, t = grow & (NT - 1);
#pragma unroll
            for (int nf = 0; nf < 4; nf++) {
                const int gcol = bn + wc * 32 + nf * 8 + 2 * (lane & 3);
                float ve = acc[mf][nf][2*h8]   + bias[gcol];
                float vo = acc[mf][nf][2*h8+1] + bias[gcol + 1];
                if (mode == 0) {
                    *(float2*)(C + (size_t)grow * ND + gcol) = make_float2(ve, vo);
                } else {
                    const int h = gcol >> 6;
                    const int dd = gcol & 63;
                    float* op = C + ((((size_t)bb * NH + h) * NT + t) * NHD) + dd;
                    if (mode == 1) {
                        const int pp = dd >> 1;
                        float cv = cosp[t * 32 + pp];
                        float sv = sinp[t * 32 + pp];
                        *(float2*)op = make_float2(ve * cv - vo * sv, ve * sv + vo * cv);
                    } else {
                        *(float2*)op = make_float2(ve, vo);
                    }
                }
            }
        }
    }
}

// ---------------------------------------------------------------------------
// Flash attention, fp32, causal (unchanged from verified round-2 kernel).
// ---------------------------------------------------------------------------
__global__ __launch_bounds__(256) void attn_kernel(
    const float* __restrict__ q, const float* __restrict__ k,
    const float* __restrict__ v, float* __restrict__ o)
{
    __shared__ float Qs[64*64];
    __shared__ float KPs[64*64];
    __shared__ float Vs[64*64];

    const int tid = threadIdx.x;
    const int qt = blockIdx.x, h = blockIdx.y, b = blockIdx.z;
    const float* qb = q + (((size_t)b*NH + h)*NT + (size_t)qt*64)*NHD;
    const float* kb = k + (((size_t)b*NH + h)*NT)*NHD;
    const float* vb = v + (((size_t)b*NH + h)*NT)*NHD;
    const int rm = tid >> 4, cm = tid & 15;
    const int pxor = (rm & 1) << 4;

    int rows[4], cols[4];
#pragma unroll
    for (int i = 0; i < 4; i++) { rows[i] = rm + 16*i; cols[i] = cm + 16*i; }

#pragma unroll
    for (int ql = 0; ql < 4; ql++) {
        int s = tid + 256*ql;
        int rowq = s >> 4;
        int c4 = (s & 15) * 4;
        float4 v4 = *(const float4*)(qb + rowq*NHD + c4);
        int col = (rowq + ((c4 >> 2) << 1)) & 63;
        Qs[(c4+0)*64+col] = v4.x; Qs[(c4+1)*64+col] = v4.y;
        Qs[(c4+2)*64+col] = v4.z; Qs[(c4+3)*64+col] = v4.w;
    }

    float m_i[4], l_i[4], acc[4][4];
#pragma unroll
    for (int i = 0; i < 4; i++) {
        m_i[i] = -1e30f; l_i[i] = 0.f;
#pragma unroll
        for (int j = 0; j < 4; j++) acc[i][j] = 0.f;
    }

    for (int kt = 0; kt <= qt; kt++) {
        __syncthreads();
#pragma unroll
        for (int ql = 0; ql < 4; ql++) {
            int s = tid + 256*ql;
            int rowq = s >> 4;
            int c4 = (s & 15) * 4;
            float4 kv = *(const float4*)(kb + (size_t)(kt*64+rowq)*NHD + c4);
            int col = (rowq + ((c4 >> 2) << 1)) & 63;
            KPs[(c4+0)*64+col] = kv.x; KPs[(c4+1)*64+col] = kv.y;
            KPs[(c4+2)*64+col] = kv.z; KPs[(c4+3)*64+col] = kv.w;
            float4 vv = *(const float4*)(vb + (size_t)(kt*64+rowq)*NHD + c4);
            *(float4*)(Vs + rowq*64 + c4) = vv;
        }
        __syncthreads();

        float sc[4][4];
#pragma unroll
        for (int i = 0; i < 4; i++)
#pragma unroll
            for (int j = 0; j < 4; j++) sc[i][j] = 0.f;
#pragma unroll 4
        for (int d = 0; d < 64; d++) {
            const int sw = (d >> 2) << 1;
            float qv[4], kv[4];
#pragma unroll
            for (int i = 0; i < 4; i++) qv[i] = Qs[d*64 + ((rows[i] + sw) & 63)];
#pragma unroll
            for (int j = 0; j < 4; j++) kv[j] = KPs[d*64 + ((cols[j] + sw) & 63)];
#pragma unroll
            for (int i = 0; i < 4; i++)
#pragma unroll
                for (int j = 0; j < 4; j++)
                    sc[i][j] = fmaf(qv[i], kv[j], sc[i][j]);
        }

#pragma unroll
        for (int i = 0; i < 4; i++) {
            const int qi = qt*64 + rows[i];
            float mloc = -1e30f;
#pragma unroll
            for (int j = 0; j < 4; j++) {
                const int kj = kt*64 + cols[j];
                float val = sc[i][j] * 0.125f;
                if (kj > qi) val = -1e30f;
                sc[i][j] = val;
                mloc = fmaxf(mloc, val);
            }
#pragma unroll
            for (int off = 8; off >= 1; off >>= 1)
                mloc = fmaxf(mloc, __shfl_xor_sync(0xffffffffu, mloc, off));
            const float m_new = fmaxf(m_i[i], mloc);
            const float alpha = __expf(m_i[i] - m_new);
            float psum = 0.f;
#pragma unroll
            for (int j = 0; j < 4; j++) {
                float p = __expf(sc[i][j] - m_new);
                sc[i][j] = p;
                psum += p;
            }
#pragma unroll
            for (int off = 8; off >= 1; off >>= 1)
                psum += __shfl_xor_sync(0xffffffffu, psum, off);
            l_i[i] = l_i[i]*alpha + psum;
            m_i[i] = m_new;
#pragma unroll
            for (int j = 0; j < 4; j++) acc[i][j] *= alpha;
        }

        __syncthreads();
#pragma unroll
        for (int i = 0; i < 4; i++)
#pragma unroll
            for (int j = 0; j < 4; j++)
                KPs[rows[i]*64 + (cols[j] ^ pxor)] = sc[i][j];
        __syncthreads();

#pragma unroll 4
        for (int kk = 0; kk < 64; kk++) {
            float pv[4], vv[4];
#pragma unroll
            for (int i = 0; i < 4; i++) pv[i] = KPs[rows[i]*64 + (kk ^ pxor)];
#pragma unroll
            for (int j = 0; j < 4; j++) vv[j] = Vs[kk*64 + cols[j]];
#pragma unroll
            for (int i = 0; i < 4; i++)
#pragma unroll
                for (int j = 0; j < 4; j++)
                    acc[i][j] = fmaf(pv[i], vv[j], acc[i][j]);
        }
    }

#pragma unroll
    for (int i = 0; i < 4; i++) {
        const float inv = 1.f / l_i[i];
        const int qi = qt*64 + rows[i];
        float* op = o + ((size_t)b*NT + qi)*ND + h*NHD;
#pragma unroll
        for (int j = 0; j < 4; j++)
            op[cols[j]] = acc[i][j] * inv;
    }
}

// ---------------------------------------------------------------------------
extern "C" void kernel_launch(void* const* d_in, const int* in_sizes, int n_in,
                              void* d_out, int out_size)
{
    (void)in_sizes; (void)n_in; (void)out_size;
    const float* x    = (const float*)d_in[0];
    const float* cosp = (const float*)d_in[1];
    const float* sinp = (const float*)d_in[2];
    const float* Wq   = (const float*)d_in[3];
    const float* bq   = (const float*)d_in[4];
    const float* Wk   = (const float*)d_in[5];
    const float* bk   = (const float*)d_in[6];
    const float* Wv   = (const float*)d_in[7];
    const float* bv   = (const float*)d_in[8];
    const float* Wo   = (const float*)d_in[9];
    const float* bo   = (const float*)d_in[10];
    float* out = (float*)d_out;

    float *qp, *kp, *vp, *ap;
    __nv_bfloat16 *xh, *xl, *wh, *wl;
    cudaGetSymbolAddress((void**)&qp, g_q);
    cudaGetSymbolAddress((void**)&kp, g_k);
    cudaGetSymbolAddress((void**)&vp, g_v);
    cudaGetSymbolAddress((void**)&ap, g_attn);
    cudaGetSymbolAddress((void**)&xh, g_xh);
    cudaGetSymbolAddress((void**)&xl, g_xl);
    cudaGetSymbolAddress((void**)&wh, g_wh);
    cudaGetSymbolAddress((void**)&wl, g_wl);

    cudaFuncSetAttribute(tgemm_kernel,
                         cudaFuncAttributeMaxDynamicSharedMemorySize, SMEM_TOTAL);

    // split inputs to bf16 hi/lo planes
    split_kernel<<<(NM*ND/4 + 255)/256, 256>>>(x, xh, xl, NM*ND/4);
    split_w_kernel<<<dim3(ND*ND/4/256, 1, 4), 256>>>(Wq, Wk, Wv, Wo, wh, wl);

    // fused QKV projection (mma.sync tensor cores) with RoPE / relayout
    tgemm_kernel<<<dim3(ND/128, NM/128, 3), 256, SMEM_TOTAL>>>(
        xh, xl, wh, wl, bq, bk, bv, qp, kp, vp, 1, cosp, sinp);

    // attention (fp32 flash)
    attn_kernel<<<dim3(NT/64, NH, NB), 256>>>(qp, kp, vp, ap);

    // split attention output, then O projection
    split_kernel<<<(NM*ND/4 + 255)/256, 256>>>(ap, xh, xl, NM*ND/4);
    tgemm_kernel<<<dim3(ND/128, NM/128, 1), 256, SMEM_TOTAL>>>(
        xh, xl, wh + (size_t)3*ND*ND, wl + (size_t)3*ND*ND,
        bo, bo, bo, out, out, out, 0, nullptr, nullptr);
}

// round 5
// speedup vs baseline: 3.0872x; 2.0324x over previous
#include <cuda_runtime.h>
#include <cuda_bf16.h>
#include <math.h>
#include <stdint.h>

#define NB 2
#define NT 2048
#define ND 1024
#define NH 16
#define NHD 64
#define NM (NB*NT)   // 4096 rows
#define QSCALE 0.18033688011112042f   // log2(e)/8

// ------------------------- scratch (__device__ globals) ---------------------
__device__ float g_attn[NB*NT*ND];
__device__ __nv_bfloat16 g_xh[NM*ND];
__device__ __nv_bfloat16 g_xl[NM*ND];
__device__ __nv_bfloat16 g_wh[4*ND*ND];
__device__ __nv_bfloat16 g_wl[4*ND*ND];
__device__ __nv_bfloat16 g_qh[NB*NH*NT*NHD];
__device__ __nv_bfloat16 g_ql[NB*NH*NT*NHD];
__device__ __nv_bfloat16 g_kh[NB*NH*NT*NHD];
__device__ __nv_bfloat16 g_kl[NB*NH*NT*NHD];
__device__ __nv_bfloat16 g_vh[NB*NH*NT*NHD];
__device__ __nv_bfloat16 g_vl[NB*NH*NT*NHD];

// ------------------------- helpers ------------------------------------------
__device__ __forceinline__ uint32_t smem_u32(const void* p) {
    uint32_t a;
    asm("{ .reg .u64 t; cvta.to.shared.u64 t, %1; cvt.u32.u64 %0, t; }"
        : "=r"(a) : "l"(p));
    return a;
}
__device__ __forceinline__ void cpasync16(uint32_t dst, const void* src) {
    asm volatile("cp.async.ca.shared.global [%0], [%1], 16;" :: "r"(dst), "l"(src));
}
#define CP_COMMIT() asm volatile("cp.async.commit_group;" ::: "memory")

__device__ __forceinline__ void mma16816(float* d, const uint32_t* a, const uint32_t* b) {
    asm volatile("mma.sync.aligned.m16n8k16.row.col.f32.bf16.bf16.f32 "
        "{%0,%1,%2,%3}, {%4,%5,%6,%7}, {%8,%9}, {%0,%1,%2,%3};"
        : "+f"(d[0]), "+f"(d[1]), "+f"(d[2]), "+f"(d[3])
        : "r"(a[0]), "r"(a[1]), "r"(a[2]), "r"(a[3]), "r"(b[0]), "r"(b[1]));
}
#define LDSM_X4(r0,r1,r2,r3,addr) \
    asm volatile("ldmatrix.sync.aligned.m8n8.x4.shared.b16 {%0,%1,%2,%3}, [%4];" \
        : "=r"(r0), "=r"(r1), "=r"(r2), "=r"(r3) : "r"(addr))
#define LDSM_X4_T(r0,r1,r2,r3,addr) \
    asm volatile("ldmatrix.sync.aligned.m8n8.x4.trans.shared.b16 {%0,%1,%2,%3}, [%4];" \
        : "=r"(r0), "=r"(r1), "=r"(r2), "=r"(r3) : "r"(addr))

// pack two f32 into bf16x2 (lo16 = x0) and the bf16x2 of residuals
__device__ __forceinline__ void pack_hilo(float x0, float x1, uint32_t& hi, uint32_t& lo) {
    asm("cvt.rn.bf16x2.f32 %0, %1, %2;" : "=r"(hi) : "f"(x1), "f"(x0));
    float h0 = __uint_as_float(hi << 16);
    float h1 = __uint_as_float(hi & 0xffff0000u);
    float r0 = x0 - h0, r1 = x1 - h1;
    asm("cvt.rn.bf16x2.f32 %0, %1, %2;" : "=r"(lo) : "f"(r1), "f"(r0));
}

// ------------------------- fp32 -> bf16 hi/lo split --------------------------
__global__ __launch_bounds__(256) void split_kernel(
    const float* __restrict__ s, __nv_bfloat16* __restrict__ h,
    __nv_bfloat16* __restrict__ l, int n4)
{
    int i = blockIdx.x * blockDim.x + threadIdx.x;
    if (i >= n4) return;
    float4 v = ((const float4*)s)[i];
    uint32_t h0, l0, h1, l1;
    pack_hilo(v.x, v.y, h0, l0);
    pack_hilo(v.z, v.w, h1, l1);
    ((uint32_t*)h)[2*i] = h0;  ((uint32_t*)h)[2*i+1] = h1;
    ((uint32_t*)l)[2*i] = l0;  ((uint32_t*)l)[2*i+1] = l1;
}

__global__ __launch_bounds__(256) void split_w_kernel(
    const float* __restrict__ w0, const float* __restrict__ w1,
    const float* __restrict__ w2, const float* __restrict__ w3,
    __nv_bfloat16* __restrict__ h, __nv_bfloat16* __restrict__ l)
{
    int z = blockIdx.z;
    const float* src = (z == 0) ? w0 : (z == 1) ? w1 : (z == 2) ? w2 : w3;
    int i = blockIdx.x * blockDim.x + threadIdx.x;
    size_t base2 = (size_t)z * (ND*ND/2);
    float4 v = ((const float4*)src)[i];
    uint32_t h0, l0, h1, l1;
    pack_hilo(v.x, v.y, h0, l0);
    pack_hilo(v.z, v.w, h1, l1);
    ((uint32_t*)h + base2)[2*i] = h0;  ((uint32_t*)h + base2)[2*i+1] = h1;
    ((uint32_t*)l + base2)[2*i] = l0;  ((uint32_t*)l + base2)[2*i+1] = l1;
}

// ------------------------- mma.sync bf16x3 GEMM ------------------------------
// Tile 128x128, BK=32, 8 warps (2x4), cp.async x2 buffer.
// modebase=1: z=0 Q (RoPE, scale QSCALE, bf16 hi/lo out), z=1 K (RoPE),
//             z=2 V (relayout) -> all to [B,H,T,HD] bf16 hi/lo planes.
// modebase=0: plain fp32 [M,ND] out (O projection).
#define BK 32
#define ROWB 80
#define TILE_BYTES (128*ROWB)
#define STAGE_BYTES (4*TILE_BYTES)
#define GSM_TOTAL (2*STAGE_BYTES)

__global__ __launch_bounds__(256, 1) void tgemm_kernel(
    const __nv_bfloat16* __restrict__ ah, const __nv_bfloat16* __restrict__ al,
    const __nv_bfloat16* __restrict__ whb, const __nv_bfloat16* __restrict__ wlb,
    const float* __restrict__ b0, const float* __restrict__ b1, const float* __restrict__ b2,
    float* __restrict__ outF,
    __nv_bfloat16* __restrict__ h0p, __nv_bfloat16* __restrict__ l0p,
    __nv_bfloat16* __restrict__ h1p, __nv_bfloat16* __restrict__ l1p,
    __nv_bfloat16* __restrict__ h2p, __nv_bfloat16* __restrict__ l2p,
    int modebase, const float* __restrict__ cosp, const float* __restrict__ sinp)
{
    extern __shared__ __align__(128) char smem[];
    const int tid = threadIdx.x;
    const int wid = tid >> 5, lane = tid & 31;
    const int z = blockIdx.z;
    const int bm = blockIdx.y * 128, bn = blockIdx.x * 128;
    const __nv_bfloat16* wh = whb + (size_t)z * ND * ND;
    const __nv_bfloat16* wl = wlb + (size_t)z * ND * ND;
    const float* bias = (z == 0) ? b0 : (z == 1) ? b1 : b2;
    __nv_bfloat16* hp = (z == 0) ? h0p : (z == 1) ? h1p : h2p;
    __nv_bfloat16* lp = (z == 0) ? l0p : (z == 1) ? l1p : l2p;
    const int mode = modebase ? ((z == 2) ? 2 : 1) : 0;
    const float oscale = (modebase && z == 0) ? QSCALE : 1.0f;

    const int wr = wid >> 2;
    const int wc = wid & 3;
    const int fr = lane >> 2;
    const int fcb = (lane & 3) * 4;

    float acc[4][4][4];
#pragma unroll
    for (int mf = 0; mf < 4; mf++)
#pragma unroll
        for (int nf = 0; nf < 4; nf++)
#pragma unroll
            for (int r = 0; r < 4; r++) acc[mf][nf][r] = 0.f;

    const uint32_t sbase = smem_u32(smem);

    auto stage_load = [&](int buf, int k0) {
        const uint32_t sb = sbase + buf * STAGE_BYTES;
        const __nv_bfloat16* srcs[4] = { ah, al, wh, wl };
#pragma unroll
        for (int tI = 0; tI < 4; tI++) {
            const int rb = (tI < 2) ? bm : bn;
#pragma unroll
            for (int i = 0; i < 2; i++) {
                int q = tid + 256 * i;
                int row = q >> 2, c = q & 3;
                cpasync16(sb + tI * TILE_BYTES + row * ROWB + c * 16,
                          srcs[tI] + (size_t)(rb + row) * ND + k0 + c * 8);
            }
        }
    };

    stage_load(0, 0);
    CP_COMMIT();

    const int NS = ND / BK;
    for (int st = 0; st < NS; st++) {
        if (st + 1 < NS) stage_load((st + 1) & 1, (st + 1) * BK);
        CP_COMMIT();
        asm volatile("cp.async.wait_group 1;" ::: "memory");
        __syncthreads();

        const char* sg = smem + (st & 1) * STAGE_BYTES;
        const char* sAh = sg;
        const char* sAl = sg + TILE_BYTES;
        const char* sBh = sg + 2 * TILE_BYTES;
        const char* sBl = sg + 3 * TILE_BYTES;

#pragma unroll
        for (int ks = 0; ks < 2; ks++) {
            const int kb = ks * 32;
            uint32_t Ah[4][4], Al[4][4], Bh[4][2], Bl[4][2];
#pragma unroll
            for (int mf = 0; mf < 4; mf++) {
                const int r0 = (wr * 64 + mf * 16 + fr) * ROWB + kb + fcb;
#pragma unroll
                for (int h8 = 0; h8 < 2; h8++)
#pragma unroll
                    for (int k8 = 0; k8 < 2; k8++) {
                        const int off = r0 + h8 * 8 * ROWB + k8 * 16;
                        Ah[mf][h8 + 2*k8] = *(const uint32_t*)(sAh + off);
                        Al[mf][h8 + 2*k8] = *(const uint32_t*)(sAl + off);
                    }
            }
#pragma unroll
            for (int nf = 0; nf < 4; nf++) {
                const int r0 = (wc * 32 + nf * 8 + fr) * ROWB + kb + fcb;
                Bh[nf][0] = *(const uint32_t*)(sBh + r0);
                Bh[nf][1] = *(const uint32_t*)(sBh + r0 + 16);
                Bl[nf][0] = *(const uint32_t*)(sBl + r0);
                Bl[nf][1] = *(const uint32_t*)(sBl + r0 + 16);
            }
#pragma unroll
            for (int mf = 0; mf < 4; mf++)
#pragma unroll
                for (int nf = 0; nf < 4; nf++)
                    mma16816(acc[mf][nf], Ah[mf], Bh[nf]);
#pragma unroll
            for (int mf = 0; mf < 4; mf++)
#pragma unroll
                for (int nf = 0; nf < 4; nf++)
                    mma16816(acc[mf][nf], Ah[mf], Bl[nf]);
#pragma unroll
            for (int mf = 0; mf < 4; mf++)
#pragma unroll
                for (int nf = 0; nf < 4; nf++)
                    mma16816(acc[mf][nf], Al[mf], Bh[nf]);
        }
        __syncthreads();
    }

    // ------------- epilogue -------------
#pragma unroll
    for (int mf = 0; mf < 4; mf++) {
#pragma unroll
        for (int h8 = 0; h8 < 2; h8++) {
            const int grow = bm + wr * 64 + mf * 16 + fr + h8 * 8;
            const int bb = grow >> 11, t = grow & (NT - 1);
#pragma unroll
            for (int nf = 0; nf < 4; nf++) {
                const int gcol = bn + wc * 32 + nf * 8 + 2 * (lane & 3);
                float ve = acc[mf][nf][2*h8]   + bias[gcol];
                float vo = acc[mf][nf][2*h8+1] + bias[gcol + 1];
                if (mode == 0) {
                    *(float2*)(outF + (size_t)grow * ND + gcol) = make_float2(ve, vo);
                } else {
                    const int h = gcol >> 6;
                    const int dd = gcol & 63;
                    float y0 = ve, y1 = vo;
                    if (mode == 1) {
                        const int pp = dd >> 1;
                        float cv = cosp[t * 32 + pp];
                        float sv = sinp[t * 32 + pp];
                        y0 = ve * cv - vo * sv;
                        y1 = ve * sv + vo * cv;
                    }
                    y0 *= oscale; y1 *= oscale;
                    uint32_t hi, lo;
                    pack_hilo(y0, y1, hi, lo);
                    size_t idx = (((size_t)bb * NH + h) * NT + t) * NHD + dd;
                    *(uint32_t*)(hp + idx) = hi;
                    *(uint32_t*)(lp + idx) = lo;
                }
            }
        }
    }
}

// ------------------------- tensor-core flash attention -----------------------
// BQ=128, BKT=64. 8 warps; warp w owns rows 16w..16w+15, all 64 cols.
// Q prescaled by log2(e)/8 -> S mma emits y = log2 of unnormalized weight.
// No-max softmax (scores bounded): P = exp2(y) via FMA-pipe poly, l = sum P.
// P hi/lo stays in registers as A-frags for PV (3-pass bf16x3 everywhere).
#define ATT_STAGE 32768   // Kh 8K | Kl 8K | Vh 8K | Vl 8K
#define ATT_SMEM  (2*ATT_STAGE)

__global__ __launch_bounds__(256, 1) void fattn_kernel(
    const __nv_bfloat16* __restrict__ Qh, const __nv_bfloat16* __restrict__ Ql,
    const __nv_bfloat16* __restrict__ Kh, const __nv_bfloat16* __restrict__ Kl,
    const __nv_bfloat16* __restrict__ Vh, const __nv_bfloat16* __restrict__ Vl,
    float* __restrict__ O)
{
    extern __shared__ __align__(128) char smem[];
    const int tid = threadIdx.x;
    const int w = tid >> 5, lane = tid & 31;
    const int fr = lane >> 2, fc = lane & 3;
    const int qt = blockIdx.x, hh = blockIdx.y, bb = blockIdx.z;
    const size_t pbase = ((size_t)bb * NH + hh) * NT * NHD;
    const size_t qbase = pbase + (size_t)qt * 128 * NHD;
    const uint32_t sb = smem_u32(smem);

    // ---- stage Q into buf0, ldmatrix to regs ----
#pragma unroll
    for (int i = 0; i < 4; i++) {
        int c = tid + 256 * i;                  // 0..1023
        int r = c >> 3, b16 = (c & 7) * 16;
        uint32_t sw = r * 128 + (b16 ^ ((r & 7) << 4));
        cpasync16(sb + sw,         Qh + qbase + r * 64 + b16 / 2);
        cpasync16(sb + 16384 + sw, Ql + qbase + r * 64 + b16 / 2);
    }
    CP_COMMIT();
    asm volatile("cp.async.wait_group 0;" ::: "memory");
    __syncthreads();

    uint32_t QHf[4][4], QLf[4][4];
    {
        int r = 16 * w + (lane & 15);
        int g2 = lane >> 4;
#pragma unroll
        for (int kf = 0; kf < 4; kf++) {
            uint32_t byte_ = (uint32_t)((kf * 32 + g2 * 16) ^ ((r & 7) << 4));
            uint32_t a = sb + r * 128 + byte_;
            LDSM_X4(QHf[kf][0], QHf[kf][1], QHf[kf][2], QHf[kf][3], a);
            LDSM_X4(QLf[kf][0], QLf[kf][1], QLf[kf][2], QLf[kf][3], a + 16384);
        }
    }
    __syncthreads();

    float acc[8][4];
#pragma unroll
    for (int nf = 0; nf < 8; nf++)
#pragma unroll
        for (int r = 0; r < 4; r++) acc[nf][r] = 0.f;
    float lsum0 = 0.f, lsum1 = 0.f;

    const int nkt = 2 * qt + 2;

    auto load_kv = [&](int kt_, int buf) {
        const uint32_t db = sb + buf * ATT_STAGE;
        const size_t src = pbase + (size_t)kt_ * 64 * NHD;
#pragma unroll
        for (int i = 0; i < 2; i++) {
            int c = tid + 256 * i;              // 0..511
            int r = c >> 3, b16 = (c & 7) * 16;
            uint32_t sw = r * 128 + (b16 ^ ((r & 7) << 4));
            size_t gs = src + r * 64 + b16 / 2;
            cpasync16(db + sw,         Kh + gs);
            cpasync16(db + 8192 + sw,  Kl + gs);
            cpasync16(db + 16384 + sw, Vh + gs);
            cpasync16(db + 24576 + sw, Vl + gs);
        }
    };

    load_kv(0, 0); CP_COMMIT();
    load_kv(1, 1); CP_COMMIT();

    const int g = lane >> 3;
    const int bxor = (lane & 7) << 4;

    for (int kt = 0; kt < nkt; kt++) {
        if (kt + 1 < nkt) { asm volatile("cp.async.wait_group 1;" ::: "memory"); }
        else              { asm volatile("cp.async.wait_group 0;" ::: "memory"); }
        __syncthreads();

        const uint32_t sg = sb + (kt & 1) * ATT_STAGE;
        const bool fullskip = (kt * 64 > qt * 128 + 16 * w + 15);

        if (!fullskip) {
            // ---------- S = Q K^T ----------
            float Sy[8][4];
#pragma unroll
            for (int nf = 0; nf < 8; nf++)
#pragma unroll
                for (int r = 0; r < 4; r++) Sy[nf][r] = 0.f;

#pragma unroll
            for (int kf = 0; kf < 4; kf++) {
                uint32_t KBh[8][2], KBl[8][2];
                const int rbase = ((g >> 1) << 3) + (lane & 7);
                const uint32_t byte_ = (uint32_t)(((kf << 5) + ((g & 1) << 4)) ^ bxor);
#pragma unroll
                for (int nfp = 0; nfp < 4; nfp++) {
                    uint32_t a = sg + (nfp * 16 + rbase) * 128 + byte_;
                    LDSM_X4(KBh[2*nfp][0], KBh[2*nfp][1], KBh[2*nfp+1][0], KBh[2*nfp+1][1], a);
                    LDSM_X4(KBl[2*nfp][0], KBl[2*nfp][1], KBl[2*nfp+1][0], KBl[2*nfp+1][1], a + 8192);
                }
#pragma unroll
                for (int nf = 0; nf < 8; nf++) mma16816(Sy[nf], QHf[kf], KBh[nf]);
#pragma unroll
                for (int nf = 0; nf < 8; nf++) mma16816(Sy[nf], QHf[kf], KBl[nf]);
#pragma unroll
                for (int nf = 0; nf < 8; nf++) mma16816(Sy[nf], QLf[kf], KBh[nf]);
            }

            // ---------- causal mask (diagonal tiles only) ----------
            if (kt * 64 + 63 > qt * 128 + 16 * w) {
                const int gr0 = qt * 128 + 16 * w + fr;
#pragma unroll
                for (int nf = 0; nf < 8; nf++) {
                    const int gc = kt * 64 + 8 * nf + 2 * fc;
#pragma unroll
                    for (int r = 0; r < 4; r++) {
                        const int row = gr0 + ((r >> 1) << 3);
                        const int col = gc + (r & 1);
                        if (col > row) Sy[nf][r] = -60.f;
                    }
                }
            }

            // ---------- exp2 + pack P hi/lo ----------
#pragma unroll
            for (int nf = 0; nf < 8; nf++) {
#pragma unroll
                for (int r = 0; r < 4; r++) {
                    float y = Sy[nf][r];
                    float t = y + 12582912.f;
                    float f = y - (t - 12582912.f);
                    int sh = (int)(__float_as_uint(t) << 23);
                    float p = fmaf(f, 0.00133336f, 0.00961813f);
                    p = fmaf(f, p, 0.05550411f);
                    p = fmaf(f, p, 0.24022651f);
                    p = fmaf(f, p, 0.69314718f);
                    p = fmaf(f, p, 1.0f);
                    float P = __int_as_float(__float_as_int(p) + sh);
                    Sy[nf][r] = P;
                    if (r < 2) lsum0 += P; else lsum1 += P;
                }
            }
            uint32_t PHf[4][4], PLf[4][4];
#pragma unroll
            for (int kf2 = 0; kf2 < 4; kf2++) {
                pack_hilo(Sy[2*kf2][0],   Sy[2*kf2][1],   PHf[kf2][0], PLf[kf2][0]);
                pack_hilo(Sy[2*kf2][2],   Sy[2*kf2][3],   PHf[kf2][1], PLf[kf2][1]);
                pack_hilo(Sy[2*kf2+1][0], Sy[2*kf2+1][1], PHf[kf2][2], PLf[kf2][2]);
                pack_hilo(Sy[2*kf2+1][2], Sy[2*kf2+1][3], PHf[kf2][3], PLf[kf2][3]);
            }

            // ---------- O += P V ----------
#pragma unroll
            for (int kf2 = 0; kf2 < 4; kf2++) {
                uint32_t VBh[8][2], VBl[8][2];
                const int rv = (kf2 << 4) + ((g & 1) << 3) + (lane & 7);
                const uint32_t vb0 = sg + 16384 + rv * 128;
#pragma unroll
                for (int nfp = 0; nfp < 4; nfp++) {
                    uint32_t byte_ = (uint32_t)(((2*nfp + (g >> 1)) << 4) ^ bxor);
                    uint32_t a = vb0 + byte_;
                    LDSM_X4_T(VBh[2*nfp][0], VBh[2*nfp][1], VBh[2*nfp+1][0], VBh[2*nfp+1][1], a);
                    LDSM_X4_T(VBl[2*nfp][0], VBl[2*nfp][1], VBl[2*nfp+1][0], VBl[2*nfp+1][1], a + 8192);
                }
#pragma unroll
                for (int nf = 0; nf < 8; nf++) mma16816(acc[nf], PHf[kf2], VBh[nf]);
#pragma unroll
                for (int nf = 0; nf < 8; nf++) mma16816(acc[nf], PHf[kf2], VBl[nf]);
#pragma unroll
                for (int nf = 0; nf < 8; nf++) mma16816(acc[nf], PLf[kf2], VBh[nf]);
            }
        }

        __syncthreads();
        if (kt + 2 < nkt) { load_kv(kt + 2, kt & 1); CP_COMMIT(); }
    }

    // ---------- finalize: reduce l over the 4 lanes of the row group ----------
    lsum0 += __shfl_xor_sync(0xffffffffu, lsum0, 1);
    lsum0 += __shfl_xor_sync(0xffffffffu, lsum0, 2);
    lsum1 += __shfl_xor_sync(0xffffffffu, lsum1, 1);
    lsum1 += __shfl_xor_sync(0xffffffffu, lsum1, 2);
    const float i0 = 1.f / lsum0, i1 = 1.f / lsum1;

    const int row0 = qt * 128 + 16 * w + fr;
    float* op0 = O + ((size_t)bb * NT + row0) * ND + hh * 64;
    float* op1 = op0 + 8 * ND;
#pragma unroll
    for (int nf = 0; nf < 8; nf++) {
        *(float2*)(op0 + 8*nf + 2*fc) = make_float2(acc[nf][0] * i0, acc[nf][1] * i0);
        *(float2*)(op1 + 8*nf + 2*fc) = make_float2(acc[nf][2] * i1, acc[nf][3] * i1);
    }
}

// ---------------------------------------------------------------------------
extern "C" void kernel_launch(void* const* d_in, const int* in_sizes, int n_in,
                              void* d_out, int out_size)
{
    (void)in_sizes; (void)n_in; (void)out_size;
    const float* x    = (const float*)d_in[0];
    const float* cosp = (const float*)d_in[1];
    const float* sinp = (const float*)d_in[2];
    const float* Wq   = (const float*)d_in[3];
    const float* bq   = (const float*)d_in[4];
    const float* Wk   = (const float*)d_in[5];
    const float* bk   = (const float*)d_in[6];
    const float* Wv   = (const float*)d_in[7];
    const float* bv   = (const float*)d_in[8];
    const float* Wo   = (const float*)d_in[9];
    const float* bo   = (const float*)d_in[10];
    float* out = (float*)d_out;

    float* ap;
    __nv_bfloat16 *xh, *xl, *wh, *wl, *qh, *ql, *kh, *kl, *vh, *vl;
    cudaGetSymbolAddress((void**)&ap, g_attn);
    cudaGetSymbolAddress((void**)&xh, g_xh);
    cudaGetSymbolAddress((void**)&xl, g_xl);
    cudaGetSymbolAddress((void**)&wh, g_wh);
    cudaGetSymbolAddress((void**)&wl, g_wl);
    cudaGetSymbolAddress((void**)&qh, g_qh);
    cudaGetSymbolAddress((void**)&ql, g_ql);
    cudaGetSymbolAddress((void**)&kh, g_kh);
    cudaGetSymbolAddress((void**)&kl, g_kl);
    cudaGetSymbolAddress((void**)&vh, g_vh);
    cudaGetSymbolAddress((void**)&vl, g_vl);

    cudaFuncSetAttribute(tgemm_kernel,
                         cudaFuncAttributeMaxDynamicSharedMemorySize, GSM_TOTAL);
    cudaFuncSetAttribute(fattn_kernel,
                         cudaFuncAttributeMaxDynamicSharedMemorySize, ATT_SMEM);

    split_kernel<<<(NM*ND/4 + 255)/256, 256>>>(x, xh, xl, NM*ND/4);
    split_w_kernel<<<dim3(ND*ND/4/256, 1, 4), 256>>>(Wq, Wk, Wv, Wo, wh, wl);

    // QKV projection -> bf16 hi/lo planes (Q pre-scaled by log2(e)/8)
    tgemm_kernel<<<dim3(ND/128, NM/128, 3), 256, GSM_TOTAL>>>(
        xh, xl, wh, wl, bq, bk, bv, nullptr,
        qh, ql, kh, kl, vh, vl, 1, cosp, sinp);

    // tensor-core flash attention
    fattn_kernel<<<dim3(NT/128, NH, NB), 256, ATT_SMEM>>>(
        qh, ql, kh, kl, vh, vl, ap);

    // O projection
    split_kernel<<<(NM*ND/4 + 255)/256, 256>>>(ap, xh, xl, NM*ND/4);
    tgemm_kernel<<<dim3(ND/128, NM/128, 1), 256, GSM_TOTAL>>>(
        xh, xl, wh + (size_t)3*ND*ND, wl + (size_t)3*ND*ND,
        bo, bo, bo, out,
        nullptr, nullptr, nullptr, nullptr, nullptr, nullptr, 0, nullptr, nullptr);
}